// round 16
// baseline (speedup 1.0000x reference)
#include <cuda_runtime.h>
#include <cuda_fp16.h>
#include <math.h>

#define NN 50000
#define NE 800000
#define C1 128
#define C2 64
#define NBLK ((NN + 255) / 256)        // 196 scan blocks
#define E4  (NE / 4)                   // 200000
#define FILL_BLOCKS ((NE + 255) / 256) // 3125
#define GEMM1_BLOCKS ((NN + 127) / 128) // 391

// ---------------- scratch (static device globals — allocation-free) --------
// g_cnt zero-initialized at load; gather2 re-zeros it each run (replay-safe).
__device__ __half g_h1[(size_t)NN * C1];    // fp16: dinv*(x@W1)
__device__ float  g_agg1[(size_t)NN * C1];  // layer1 output (post relu), fp32
__device__ __half g_h2[(size_t)NN * C2];    // fp16: dinv*(agg1@W2)
__device__ float  g_dinv[NN];
__device__ int    g_cnt[NN];
__device__ int    g_rowstart[NN + 1];
__device__ int    g_cursor[NN];
__device__ int    g_src[NE];
__device__ int    g_bsum[NBLK];
__device__ unsigned g_gemm1_done;           // gemm1 completion counter (join)

// ---------------- tf32 helpers ----------------------------------------------
__device__ __forceinline__ unsigned f2tf32(float f) {
    unsigned r;
    asm("cvt.rna.tf32.f32 %0, %1;" : "=r"(r) : "f"(f));
    return r;
}

__device__ __forceinline__ void mma_tf32(float* d, const unsigned* a, const unsigned* b) {
    asm volatile(
        "mma.sync.aligned.m16n8k8.row.col.f32.tf32.tf32.f32 "
        "{%0,%1,%2,%3}, {%4,%5,%6,%7}, {%8,%9}, {%0,%1,%2,%3};"
        : "+f"(d[0]), "+f"(d[1]), "+f"(d[2]), "+f"(d[3])
        : "r"(a[0]), "r"(a[1]), "r"(a[2]), "r"(a[3]), "r"(b[0]), "r"(b[1]));
}

// release-publish one block's writes (after __syncthreads) / acquire-poll
__device__ __forceinline__ void block_report(unsigned* ctr) {
    asm volatile("red.release.gpu.global.add.u32 [%0], 1;" :: "l"(ctr) : "memory");
}
__device__ __forceinline__ unsigned acquire_load(const unsigned* p) {
    unsigned v;
    asm volatile("ld.acquire.gpu.global.u32 %0, [%1];" : "=r"(v) : "l"(p) : "memory");
    return v;
}

// ---------------- CSR construction ------------------------------------------
__global__ void k_hist(const int4* __restrict__ col4, int* cnt, int e4) {
    cudaGridDependencySynchronize();   // prior replay's gather2 (cnt reset)
    int i = blockIdx.x * blockDim.x + threadIdx.x;
    if (i < e4) {
        int4 c = __ldg(&col4[i]);
        atomicAdd(&cnt[c.x], 1);
        atomicAdd(&cnt[c.y], 1);
        atomicAdd(&cnt[c.z], 1);
        atomicAdd(&cnt[c.w], 1);
    }
}

// dinv from degrees only — unblocks gemm1 before scan/finalize/fill run.
__global__ void k_dinv(const int* __restrict__ cnt, float* dinv, int n) {
    cudaGridDependencySynchronize();   // hist complete
    int i = blockIdx.x * blockDim.x + threadIdx.x;
    if (i < n) dinv[i] = rsqrtf((float)cnt[i] + 1.0f);
}

__global__ void k_scan_block(const int* __restrict__ cnt, int* ex, int* bsum, int n) {
    cudaGridDependencySynchronize();   // gemm1's EARLY trigger (cnt ready via hist)
    __shared__ int sh[256];
    int i = blockIdx.x * 256 + threadIdx.x;
    int v = (i < n) ? cnt[i] : 0;
    sh[threadIdx.x] = v;
    __syncthreads();
    for (int off = 1; off < 256; off <<= 1) {
        int t = (threadIdx.x >= off) ? sh[threadIdx.x - off] : 0;
        __syncthreads();
        sh[threadIdx.x] += t;
        __syncthreads();
    }
    int inc = sh[threadIdx.x];
    if (i < n) ex[i] = inc - v;
    if (threadIdx.x == 255) bsum[blockIdx.x] = inc;
}

__global__ void k_finalize(int* rowstart, int* cursor, const int* __restrict__ bsum,
                           int n, int e) {
    cudaGridDependencySynchronize();
    __shared__ int sw[8];
    const int b = blockIdx.x;
    const int t = threadIdx.x;
    const int lane = t & 31;
    int v = (t < b && t < NBLK) ? bsum[t] : 0;
#pragma unroll
    for (int off = 16; off > 0; off >>= 1) v += __shfl_down_sync(0xffffffffu, v, off);
    if (lane == 0) sw[t >> 5] = v;
    __syncthreads();
    if (t < 32) {
        int w = (t < 8) ? sw[t] : 0;
#pragma unroll
        for (int off = 4; off > 0; off >>= 1) w += __shfl_down_sync(0xffffffffu, w, off);
        if (t == 0) sw[0] = w;
    }
    __syncthreads();
    int boff = sw[0];
    int i = b * 256 + t;
    if (i < n) {
        int rs = rowstart[i] + boff;
        rowstart[i] = rs;
        cursor[i]   = rs;
    }
    if (i == 0) rowstart[n] = e;
}

// fill: runs concurrently with gemm1 (both after finalize/dinv respectively).
// Completes normally; gather1's gridsync guarantees src is visible.
__global__ void k_fill(const int* __restrict__ rows, const int* __restrict__ cols,
                       int* cursor, int* src, int e) {
    cudaGridDependencySynchronize();             // finalize done
    int i = blockIdx.x * blockDim.x + threadIdx.x;
    if (i < e) {
        int p = atomicAdd(&cursor[cols[i]], 1);
        src[p] = rows[i];
    }
}

// ---------------- tensor-core transform: Hs = fp16(dinv_row * (X @ W)) ------
// TF32 mma m16n8k8. One CTA: 128 rows x full C. 8 warps (4M x 2N).
// W staged in padded smem; A fragments loaded directly from global.
// MODE 0 (gemm1): gridsync on k_dinv, TRIGGER EARLY (scan/fin/fill overlap),
//                 publish per-block completion for gather1's join.
// MODE 1 (gemm2): plain gridsync on gather1.
template <int C, int MODE>
__global__ __launch_bounds__(256)
void k_gemm_tc(const float* __restrict__ X, const float* __restrict__ W,
               const float* __restrict__ dinv, __half* __restrict__ Hs, int n) {
    cudaGridDependencySynchronize();             // MODE0: dinv ready; MODE1: gather1
    if (MODE == 0) cudaTriggerProgrammaticLaunchCompletion();  // release CSR chain
    constexpr int K  = 128;
    constexpr int BM = 128;
    constexpr int WP = C + 8;     // W pitch: B-frag banks distinct
    constexpr int WN = C / 2;     // warp N tile
    constexpr int NF = WN / 8;    // n8 fragments per warp

    extern __shared__ float sm[];
    float* Wsm = sm;              // [K][WP]

    const int tid  = threadIdx.x;
    const int wid  = tid >> 5;
    const int lane = tid & 31;
    const int wm   = wid >> 1;
    const int wn   = wid & 1;
    const int row0 = blockIdx.x * BM;
    const int g    = lane >> 2;
    const int t    = lane & 3;

    for (int i = tid; i < K * (C / 4); i += 256) {
        int r = i / (C / 4), v = i % (C / 4);
        float4 w = __ldg(reinterpret_cast<const float4*>(W + (size_t)r * C) + v);
        float* dst = Wsm + r * WP + v * 4;
        dst[0] = __uint_as_float(f2tf32(w.x));
        dst[1] = __uint_as_float(f2tf32(w.y));
        dst[2] = __uint_as_float(f2tf32(w.z));
        dst[3] = __uint_as_float(f2tf32(w.w));
    }
    __syncthreads();

    const int r00 = row0 + wm * 32 + g;
    const int r01 = r00 + 8;
    const int r10 = r00 + 16;
    const int r11 = r00 + 24;
    const bool v00 = r00 < n, v01 = r01 < n, v10 = r10 < n, v11 = r11 < n;
    const float* p00 = X + (size_t)r00 * K + t;
    const float* p01 = X + (size_t)r01 * K + t;
    const float* p10 = X + (size_t)r10 * K + t;
    const float* p11 = X + (size_t)r11 * K + t;

    float acc[2][NF][4];
#pragma unroll
    for (int mi = 0; mi < 2; mi++)
#pragma unroll
        for (int nf = 0; nf < NF; nf++)
#pragma unroll
            for (int q = 0; q < 4; q++) acc[mi][nf][q] = 0.0f;

#pragma unroll
    for (int k0 = 0; k0 < K; k0 += 8) {
        unsigned a[2][4];
        a[0][0] = f2tf32(v00 ? __ldg(p00 + k0)     : 0.f);
        a[0][1] = f2tf32(v01 ? __ldg(p01 + k0)     : 0.f);
        a[0][2] = f2tf32(v00 ? __ldg(p00 + k0 + 4) : 0.f);
        a[0][3] = f2tf32(v01 ? __ldg(p01 + k0 + 4) : 0.f);
        a[1][0] = f2tf32(v10 ? __ldg(p10 + k0)     : 0.f);
        a[1][1] = f2tf32(v11 ? __ldg(p11 + k0)     : 0.f);
        a[1][2] = f2tf32(v10 ? __ldg(p10 + k0 + 4) : 0.f);
        a[1][3] = f2tf32(v11 ? __ldg(p11 + k0 + 4) : 0.f);

        unsigned b[NF][2];
#pragma unroll
        for (int nf = 0; nf < NF; nf++) {
            int c = wn * WN + nf * 8 + g;
            b[nf][0] = __float_as_uint(Wsm[(k0 + t) * WP + c]);
            b[nf][1] = __float_as_uint(Wsm[(k0 + t + 4) * WP + c]);
        }
#pragma unroll
        for (int mi = 0; mi < 2; mi++)
#pragma unroll
            for (int nf = 0; nf < NF; nf++)
                mma_tf32(acc[mi][nf], a[mi], b[nf]);
    }

#pragma unroll
    for (int mi = 0; mi < 2; mi++) {
        int rA = row0 + wm * 32 + mi * 16 + g;
        int rB = rA + 8;
        float dA = (rA < n) ? dinv[rA] : 0.f;
        float dB = (rB < n) ? dinv[rB] : 0.f;
#pragma unroll
        for (int nf = 0; nf < NF; nf++) {
            int c = wn * WN + nf * 8 + 2 * t;
            if (rA < n) {
                __half2 hA = __float22half2_rn(
                    make_float2(dA * acc[mi][nf][0], dA * acc[mi][nf][1]));
                *reinterpret_cast<__half2*>(Hs + (size_t)rA * C + c) = hA;
            }
            if (rB < n) {
                __half2 hB = __float22half2_rn(
                    make_float2(dB * acc[mi][nf][2], dB * acc[mi][nf][3]));
                *reinterpret_cast<__half2*>(Hs + (size_t)rB * C + c) = hB;
            }
        }
    }

    if (MODE == 0) {
        __syncthreads();   // all Hs stores in this block issued
        if (tid == 0) block_report(&g_gemm1_done);
    }
}

// ---------------- CSR gather (fp16 Hs, shfl-batched indices) ----------------
// WAIT: acquire-join on gemm1 counter (gather1; its gridsync only covers fill).
// RESET: gather2 re-zeros counter + cnt for the next graph replay.
template <int C, bool RELU, bool WAIT, bool RESET>
__global__ void k_gather(const __half* __restrict__ Hs, const int* __restrict__ rowstart,
                         const int* __restrict__ src, const float* __restrict__ dinv,
                         const float* __restrict__ bias, float* __restrict__ out,
                         int* cnt, int n) {
    cudaGridDependencySynchronize();   // predecessor complete (fill / gemm2)
    if (RESET) {
        if (blockIdx.x == 0 && threadIdx.x == 0) g_gemm1_done = 0;
        if (blockIdx.x < NBLK) {
            int i = blockIdx.x * 256 + threadIdx.x;
            if (i < NN) cnt[i] = 0;
        }
    }
    if (WAIT) {
        if (threadIdx.x == 0) {
            while (acquire_load(&g_gemm1_done) < (unsigned)GEMM1_BLOCKS) { }
        }
        __syncthreads();
    }
    int warp = (blockIdx.x * blockDim.x + threadIdx.x) >> 5;
    int lane = threadIdx.x & 31;
    if (warp >= n) return;
    const int node = warp;
    const int s = rowstart[node];
    const int deg = rowstart[node + 1] - s;

    if (C == 128) {
        uint2 hv = __ldg(reinterpret_cast<const uint2*>(Hs + (size_t)node * 128) + lane);
        float2 p0 = __half22float2(*reinterpret_cast<__half2*>(&hv.x));
        float2 p1 = __half22float2(*reinterpret_cast<__half2*>(&hv.y));
        float4 acc = make_float4(p0.x, p0.y, p1.x, p1.y);

        for (int base = 0; base < deg; base += 32) {
            int m = min(32, deg - base);
            int myidx = (base + lane < deg) ? __ldg(&src[s + base + lane]) : 0;
            for (int k = 0; k < m; k++) {
                int r = __shfl_sync(0xffffffffu, myidx, k);
                uint2 v = __ldg(reinterpret_cast<const uint2*>(Hs + (size_t)r * 128) + lane);
                float2 q0 = __half22float2(*reinterpret_cast<__half2*>(&v.x));
                float2 q1 = __half22float2(*reinterpret_cast<__half2*>(&v.y));
                acc.x += q0.x; acc.y += q0.y; acc.z += q1.x; acc.w += q1.y;
            }
        }
        float di = dinv[node];
        float4 bv = __ldg(reinterpret_cast<const float4*>(bias) + lane);
        float4 o = make_float4(fmaf(di, acc.x, bv.x), fmaf(di, acc.y, bv.y),
                               fmaf(di, acc.z, bv.z), fmaf(di, acc.w, bv.w));
        if (RELU) {
            o.x = fmaxf(o.x, 0.f); o.y = fmaxf(o.y, 0.f);
            o.z = fmaxf(o.z, 0.f); o.w = fmaxf(o.w, 0.f);
        }
        reinterpret_cast<float4*>(out)[(size_t)node * 32 + lane] = o;
    } else {
        unsigned hv = __ldg(reinterpret_cast<const unsigned*>(Hs + (size_t)node * 64) + lane);
        float2 acc = __half22float2(*reinterpret_cast<__half2*>(&hv));

        for (int base = 0; base < deg; base += 32) {
            int m = min(32, deg - base);
            int myidx = (base + lane < deg) ? __ldg(&src[s + base + lane]) : 0;
            for (int k = 0; k < m; k++) {
                int r = __shfl_sync(0xffffffffu, myidx, k);
                unsigned v = __ldg(reinterpret_cast<const unsigned*>(Hs + (size_t)r * 64) + lane);
                float2 q = __half22float2(*reinterpret_cast<__half2*>(&v));
                acc.x += q.x; acc.y += q.y;
            }
        }
        float di = dinv[node];
        float2 bv = __ldg(reinterpret_cast<const float2*>(bias) + lane);
        float2 o = make_float2(fmaf(di, acc.x, bv.x), fmaf(di, acc.y, bv.y));
        if (RELU) { o.x = fmaxf(o.x, 0.f); o.y = fmaxf(o.y, 0.f); }
        reinterpret_cast<float2*>(out)[(size_t)node * 32 + lane] = o;
    }
}

// ---------------- PDL launch helper ------------------------------------------
template <typename F, typename... Args>
static inline void launch_pdl(F func, int grid, int block, size_t smem, Args... args) {
    cudaLaunchConfig_t cfg = {};
    cfg.gridDim = dim3(grid, 1, 1);
    cfg.blockDim = dim3(block, 1, 1);
    cfg.dynamicSmemBytes = smem;
    cfg.stream = 0;
    cudaLaunchAttribute attr[1];
    attr[0].id = cudaLaunchAttributeProgrammaticStreamSerialization;
    attr[0].val.programmaticStreamSerializationAllowed = 1;
    cfg.attrs = attr;
    cfg.numAttrs = 1;
    cudaLaunchKernelEx(&cfg, func, args...);
}

// ---------------- launch -----------------------------------------------------
extern "C" void kernel_launch(void* const* d_in, const int* in_sizes, int n_in,
                              void* d_out, int out_size) {
    const float* x  = (const float*)d_in[0];
    const int*   ei = (const int*)d_in[1];   // rows = ei, cols = ei + NE
    const float* W1 = (const float*)d_in[2];
    const float* b1 = (const float*)d_in[3];
    const float* W2 = (const float*)d_in[4];
    const float* b2 = (const float*)d_in[5];
    float* out = (float*)d_out;

    const int* rows = ei;
    const int* cols = ei + NE;
    const int4* cols4 = (const int4*)(ei + NE);

    __half *h1, *h2;
    float *agg1, *dinv;
    int *cnt, *rowstart, *cursor, *srcA, *bsum;
    cudaGetSymbolAddress((void**)&h1,       g_h1);
    cudaGetSymbolAddress((void**)&agg1,     g_agg1);
    cudaGetSymbolAddress((void**)&h2,       g_h2);
    cudaGetSymbolAddress((void**)&dinv,     g_dinv);
    cudaGetSymbolAddress((void**)&cnt,      g_cnt);
    cudaGetSymbolAddress((void**)&rowstart, g_rowstart);
    cudaGetSymbolAddress((void**)&cursor,   g_cursor);
    cudaGetSymbolAddress((void**)&srcA,     g_src);
    cudaGetSymbolAddress((void**)&bsum,     g_bsum);

    const int T = 256;
    const int SMEM1 = (128 * (C1 + 8)) * (int)sizeof(float);  // 69632
    const int SMEM2 = (128 * (C2 + 8)) * (int)sizeof(float);  // 36864
    cudaFuncSetAttribute((const void*)k_gemm_tc<C1, 0>,
                         cudaFuncAttributeMaxDynamicSharedMemorySize, SMEM1);
    cudaFuncSetAttribute((const void*)k_gemm_tc<C2, 1>,
                         cudaFuncAttributeMaxDynamicSharedMemorySize, SMEM2);

    const int GB = GEMM1_BLOCKS;              // gemm blocks (391)
    const int GW = (NN * 32 + T - 1) / T;     // gather blocks (warp/node)

    // ---- degree + dinv first: unblocks gemm1 before scan/fin/fill ----
    launch_pdl(k_hist, (E4 + T - 1) / T, T, 0, cols4, cnt, E4);
    launch_pdl(k_dinv, NBLK, 256, 0, (const int*)cnt, dinv, NN);

    // ---- gemm1: gridsync(dinv) then TRIGGERS EARLY -> CSR chain overlaps ----
    launch_pdl(k_gemm_tc<C1, 0>, GB, T, SMEM1, x, W1, (const float*)dinv, h1, NN);

    // ---- CSR chain (runs concurrently with gemm1) ----
    launch_pdl(k_scan_block, NBLK, 256, 0, (const int*)cnt, rowstart, bsum, NN);
    launch_pdl(k_finalize, NBLK, 256, 0, rowstart, cursor, (const int*)bsum, NN, NE);
    launch_pdl(k_fill, FILL_BLOCKS, T, 0, rows, cols, cursor, srcA, NE);

    // ---- layer 1 aggregate: gridsync(fill) + counter-join on gemm1 ----
    launch_pdl(k_gather<C1, true, true, false>, GW, T, 0, (const __half*)h1,
               (const int*)rowstart, (const int*)srcA, (const float*)dinv,
               b1, agg1, cnt, NN);

    // ---- layer 2 ----
    launch_pdl(k_gemm_tc<C2, 1>, GB, T, SMEM2, (const float*)agg1, W2,
               (const float*)dinv, h2, NN);
    launch_pdl(k_gather<C2, false, false, true>, GW, T, 0, (const __half*)h2,
               (const int*)rowstart, (const int*)srcA, (const float*)dinv,
               b2, out, cnt, NN);
}

// round 17
// speedup vs baseline: 1.0699x; 1.0699x over previous
#include <cuda_runtime.h>
#include <cuda_fp16.h>
#include <math.h>

#define NN 50000
#define NE 800000
#define C1 128
#define C2 64
#define NBLK ((NN + 255) / 256)        // 196 scan blocks
#define E4  (NE / 4)                   // 200000
#define FILL_BLOCKS ((NE + 255) / 256) // 3125

// ---------------- scratch (static device globals — allocation-free) --------
// g_cnt zero-initialized at load; gather2 re-zeros it each run (replay-safe).
__device__ __half g_h1[(size_t)NN * C1];    // fp16: dinv*(x@W1)
__device__ float  g_agg1[(size_t)NN * C1];  // layer1 output (post relu), fp32
__device__ __half g_h2[(size_t)NN * C2];    // fp16: dinv*(agg1@W2)
__device__ float  g_dinv[NN];
__device__ int    g_cnt[NN];
__device__ int    g_rowstart[NN + 1];
__device__ int    g_cursor[NN];
__device__ int    g_src[NE];
__device__ int    g_bsum[NBLK];
__device__ unsigned g_fill_done;            // fill completion counter (join)

// ---------------- tf32 helpers ----------------------------------------------
__device__ __forceinline__ unsigned f2tf32(float f) {
    unsigned r;
    asm("cvt.rna.tf32.f32 %0, %1;" : "=r"(r) : "f"(f));
    return r;
}

__device__ __forceinline__ void mma_tf32(float* d, const unsigned* a, const unsigned* b) {
    asm volatile(
        "mma.sync.aligned.m16n8k8.row.col.f32.tf32.tf32.f32 "
        "{%0,%1,%2,%3}, {%4,%5,%6,%7}, {%8,%9}, {%0,%1,%2,%3};"
        : "+f"(d[0]), "+f"(d[1]), "+f"(d[2]), "+f"(d[3])
        : "r"(a[0]), "r"(a[1]), "r"(a[2]), "r"(a[3]), "r"(b[0]), "r"(b[1]));
}

// release-publish one block's writes (after __syncthreads) / acquire-poll
__device__ __forceinline__ void block_report(unsigned* ctr) {
    asm volatile("red.release.gpu.global.add.u32 [%0], 1;" :: "l"(ctr) : "memory");
}
__device__ __forceinline__ unsigned acquire_load(const unsigned* p) {
    unsigned v;
    asm volatile("ld.acquire.gpu.global.u32 %0, [%1];" : "=r"(v) : "l"(p) : "memory");
    return v;
}

// ---------------- CSR construction ------------------------------------------
__global__ void k_hist(const int4* __restrict__ col4, int* cnt, int e4) {
    cudaGridDependencySynchronize();   // prior node complete (cnt zeroed)
    int i = blockIdx.x * blockDim.x + threadIdx.x;
    if (i < e4) {
        int4 c = __ldg(&col4[i]);
        atomicAdd(&cnt[c.x], 1);
        atomicAdd(&cnt[c.y], 1);
        atomicAdd(&cnt[c.z], 1);
        atomicAdd(&cnt[c.w], 1);
    }
}

__global__ void k_scan_block(const int* __restrict__ cnt, int* ex, int* bsum, int n) {
    cudaGridDependencySynchronize();
    __shared__ int sh[256];
    int i = blockIdx.x * 256 + threadIdx.x;
    int v = (i < n) ? cnt[i] : 0;
    sh[threadIdx.x] = v;
    __syncthreads();
    for (int off = 1; off < 256; off <<= 1) {
        int t = (threadIdx.x >= off) ? sh[threadIdx.x - off] : 0;
        __syncthreads();
        sh[threadIdx.x] += t;
        __syncthreads();
    }
    int inc = sh[threadIdx.x];
    if (i < n) ex[i] = inc - v;
    if (threadIdx.x == 255) bsum[blockIdx.x] = inc;
}

__global__ void k_finalize(int* rowstart, int* cursor, const int* __restrict__ bsum,
                           const int* __restrict__ cnt, float* dinv, int n, int e) {
    cudaGridDependencySynchronize();
    __shared__ int sw[8];
    const int b = blockIdx.x;
    const int t = threadIdx.x;
    const int lane = t & 31;
    int v = (t < b && t < NBLK) ? bsum[t] : 0;
#pragma unroll
    for (int off = 16; off > 0; off >>= 1) v += __shfl_down_sync(0xffffffffu, v, off);
    if (lane == 0) sw[t >> 5] = v;
    __syncthreads();
    if (t < 32) {
        int w = (t < 8) ? sw[t] : 0;
#pragma unroll
        for (int off = 4; off > 0; off >>= 1) w += __shfl_down_sync(0xffffffffu, w, off);
        if (t == 0) sw[0] = w;
    }
    __syncthreads();
    int boff = sw[0];
    int i = b * 256 + t;
    if (i < n) {
        int rs = rowstart[i] + boff;
        rowstart[i] = rs;
        cursor[i]   = rs;
        dinv[i]     = rsqrtf((float)cnt[i] + 1.0f);
    }
    if (i == 0) rowstart[n] = e;
}

// fill: gridsync (finalize done -> cursor/dinv ready), THEN trigger so the
// following PDL gemm1 (reads dinv) overlaps fill's execution. One release-red
// per block publishes this block's scattered src stores (join for gather1).
__global__ void k_fill(const int* __restrict__ rows, const int* __restrict__ cols,
                       int* cursor, int* src, unsigned* fill_done, int e) {
    cudaGridDependencySynchronize();             // finalize done
    cudaTriggerProgrammaticLaunchCompletion();   // release gemm1 now
    int i = blockIdx.x * blockDim.x + threadIdx.x;
    if (i < e) {
        int p = atomicAdd(&cursor[cols[i]], 1);
        src[p] = rows[i];
    }
    __syncthreads();                             // block stores happen-before t0
    if (threadIdx.x == 0) block_report(fill_done);
}

// ---------------- tensor-core transform: Hs = fp16(dinv_row * (X @ W)) ------
// TF32 mma m16n8k8. One CTA: 128 rows x full C. 8 warps (4M x 2N).
// W staged in padded smem (reused by all warps); A fragments loaded DIRECTLY
// from global (zero intra-block reuse -> staging X only cost occupancy).
template <int C, bool SYNC>
__global__ __launch_bounds__(256)
void k_gemm_tc(const float* __restrict__ X, const float* __restrict__ W,
               const float* __restrict__ dinv, __half* __restrict__ Hs, int n) {
    if (SYNC) cudaGridDependencySynchronize();   // layer2: wait gather1
    constexpr int K  = 128;
    constexpr int BM = 128;
    constexpr int WP = C + 8;     // W pitch: B-frag banks distinct
    constexpr int WN = C / 2;     // warp N tile
    constexpr int NF = WN / 8;    // n8 fragments per warp

    extern __shared__ float sm[];
    float* Wsm = sm;              // [K][WP]

    const int tid  = threadIdx.x;
    const int wid  = tid >> 5;
    const int lane = tid & 31;
    const int wm   = wid >> 1;
    const int wn   = wid & 1;
    const int row0 = blockIdx.x * BM;
    const int g    = lane >> 2;
    const int t    = lane & 3;

    // stage W (tf32-converted, reused by all warps)
    for (int i = tid; i < K * (C / 4); i += 256) {
        int r = i / (C / 4), v = i % (C / 4);
        float4 w = __ldg(reinterpret_cast<const float4*>(W + (size_t)r * C) + v);
        float* dst = Wsm + r * WP + v * 4;
        dst[0] = __uint_as_float(f2tf32(w.x));
        dst[1] = __uint_as_float(f2tf32(w.y));
        dst[2] = __uint_as_float(f2tf32(w.z));
        dst[3] = __uint_as_float(f2tf32(w.w));
    }
    __syncthreads();

    // A rows this lane touches (2 per m16 frag, 2 frags)
    const int r00 = row0 + wm * 32 + g;
    const int r01 = r00 + 8;
    const int r10 = r00 + 16;
    const int r11 = r00 + 24;
    const bool v00 = r00 < n, v01 = r01 < n, v10 = r10 < n, v11 = r11 < n;
    const float* p00 = X + (size_t)r00 * K + t;
    const float* p01 = X + (size_t)r01 * K + t;
    const float* p10 = X + (size_t)r10 * K + t;
    const float* p11 = X + (size_t)r11 * K + t;

    float acc[2][NF][4];
#pragma unroll
    for (int mi = 0; mi < 2; mi++)
#pragma unroll
        for (int nf = 0; nf < NF; nf++)
#pragma unroll
            for (int q = 0; q < 4; q++) acc[mi][nf][q] = 0.0f;

#pragma unroll
    for (int k0 = 0; k0 < K; k0 += 8) {
        unsigned a[2][4];
        a[0][0] = f2tf32(v00 ? __ldg(p00 + k0)     : 0.f);
        a[0][1] = f2tf32(v01 ? __ldg(p01 + k0)     : 0.f);
        a[0][2] = f2tf32(v00 ? __ldg(p00 + k0 + 4) : 0.f);
        a[0][3] = f2tf32(v01 ? __ldg(p01 + k0 + 4) : 0.f);
        a[1][0] = f2tf32(v10 ? __ldg(p10 + k0)     : 0.f);
        a[1][1] = f2tf32(v11 ? __ldg(p11 + k0)     : 0.f);
        a[1][2] = f2tf32(v10 ? __ldg(p10 + k0 + 4) : 0.f);
        a[1][3] = f2tf32(v11 ? __ldg(p11 + k0 + 4) : 0.f);

        unsigned b[NF][2];
#pragma unroll
        for (int nf = 0; nf < NF; nf++) {
            int c = wn * WN + nf * 8 + g;
            b[nf][0] = __float_as_uint(Wsm[(k0 + t) * WP + c]);
            b[nf][1] = __float_as_uint(Wsm[(k0 + t + 4) * WP + c]);
        }
#pragma unroll
        for (int mi = 0; mi < 2; mi++)
#pragma unroll
            for (int nf = 0; nf < NF; nf++)
                mma_tf32(acc[mi][nf], a[mi], b[nf]);
    }

    // epilogue: Hs = fp16(dinv_row * acc)
#pragma unroll
    for (int mi = 0; mi < 2; mi++) {
        int rA = row0 + wm * 32 + mi * 16 + g;
        int rB = rA + 8;
        float dA = (rA < n) ? dinv[rA] : 0.f;
        float dB = (rB < n) ? dinv[rB] : 0.f;
#pragma unroll
        for (int nf = 0; nf < NF; nf++) {
            int c = wn * WN + nf * 8 + 2 * t;
            if (rA < n) {
                __half2 hA = __float22half2_rn(
                    make_float2(dA * acc[mi][nf][0], dA * acc[mi][nf][1]));
                *reinterpret_cast<__half2*>(Hs + (size_t)rA * C + c) = hA;
            }
            if (rB < n) {
                __half2 hB = __float22half2_rn(
                    make_float2(dB * acc[mi][nf][2], dB * acc[mi][nf][3]));
                *reinterpret_cast<__half2*>(Hs + (size_t)rB * C + c) = hB;
            }
        }
    }
}

// ---------------- CSR gather (fp16 Hs, shfl-batched indices) ----------------
// WAIT: acquire-join on fill counter (gather1).
// RESET: gather2 re-zeros fill counter + cnt for the next graph replay.
template <int C, bool RELU, bool WAIT, bool RESET>
__global__ void k_gather(const __half* __restrict__ Hs, const int* __restrict__ rowstart,
                         const int* __restrict__ src, const float* __restrict__ dinv,
                         const float* __restrict__ bias, float* __restrict__ out,
                         unsigned* fill_done, int* cnt, int n) {
    cudaGridDependencySynchronize();   // predecessor gemm complete
    if (RESET) {
        if (blockIdx.x == 0 && threadIdx.x == 0) *fill_done = 0;
        if (blockIdx.x < NBLK) {
            int i = blockIdx.x * 256 + threadIdx.x;
            if (i < NN) cnt[i] = 0;
        }
    }
    if (WAIT) {
        if (threadIdx.x == 0) {
            while (acquire_load(fill_done) < (unsigned)FILL_BLOCKS) { }
        }
        __syncthreads();
    }
    int warp = (blockIdx.x * blockDim.x + threadIdx.x) >> 5;
    int lane = threadIdx.x & 31;
    if (warp >= n) return;
    const int node = warp;
    const int s = rowstart[node];
    const int deg = rowstart[node + 1] - s;

    if (C == 128) {
        uint2 hv = __ldg(reinterpret_cast<const uint2*>(Hs + (size_t)node * 128) + lane);
        float2 p0 = __half22float2(*reinterpret_cast<__half2*>(&hv.x));
        float2 p1 = __half22float2(*reinterpret_cast<__half2*>(&hv.y));
        float4 acc = make_float4(p0.x, p0.y, p1.x, p1.y);

        for (int base = 0; base < deg; base += 32) {
            int m = min(32, deg - base);
            int myidx = (base + lane < deg) ? __ldg(&src[s + base + lane]) : 0;
            for (int k = 0; k < m; k++) {
                int r = __shfl_sync(0xffffffffu, myidx, k);
                uint2 v = __ldg(reinterpret_cast<const uint2*>(Hs + (size_t)r * 128) + lane);
                float2 q0 = __half22float2(*reinterpret_cast<__half2*>(&v.x));
                float2 q1 = __half22float2(*reinterpret_cast<__half2*>(&v.y));
                acc.x += q0.x; acc.y += q0.y; acc.z += q1.x; acc.w += q1.y;
            }
        }
        float di = dinv[node];
        float4 bv = __ldg(reinterpret_cast<const float4*>(bias) + lane);
        float4 o = make_float4(fmaf(di, acc.x, bv.x), fmaf(di, acc.y, bv.y),
                               fmaf(di, acc.z, bv.z), fmaf(di, acc.w, bv.w));
        if (RELU) {
            o.x = fmaxf(o.x, 0.f); o.y = fmaxf(o.y, 0.f);
            o.z = fmaxf(o.z, 0.f); o.w = fmaxf(o.w, 0.f);
        }
        reinterpret_cast<float4*>(out)[(size_t)node * 32 + lane] = o;
    } else {
        unsigned hv = __ldg(reinterpret_cast<const unsigned*>(Hs + (size_t)node * 64) + lane);
        float2 acc = __half22float2(*reinterpret_cast<__half2*>(&hv));

        for (int base = 0; base < deg; base += 32) {
            int m = min(32, deg - base);
            int myidx = (base + lane < deg) ? __ldg(&src[s + base + lane]) : 0;
            for (int k = 0; k < m; k++) {
                int r = __shfl_sync(0xffffffffu, myidx, k);
                unsigned v = __ldg(reinterpret_cast<const unsigned*>(Hs + (size_t)r * 64) + lane);
                float2 q = __half22float2(*reinterpret_cast<__half2*>(&v));
                acc.x += q.x; acc.y += q.y;
            }
        }
        float di = dinv[node];
        float2 bv = __ldg(reinterpret_cast<const float2*>(bias) + lane);
        float2 o = make_float2(fmaf(di, acc.x, bv.x), fmaf(di, acc.y, bv.y));
        if (RELU) { o.x = fmaxf(o.x, 0.f); o.y = fmaxf(o.y, 0.f); }
        reinterpret_cast<float2*>(out)[(size_t)node * 32 + lane] = o;
    }
}

// ---------------- PDL launch helper ------------------------------------------
template <typename F, typename... Args>
static inline void launch_pdl(F func, int grid, int block, size_t smem, Args... args) {
    cudaLaunchConfig_t cfg = {};
    cfg.gridDim = dim3(grid, 1, 1);
    cfg.blockDim = dim3(block, 1, 1);
    cfg.dynamicSmemBytes = smem;
    cfg.stream = 0;
    cudaLaunchAttribute attr[1];
    attr[0].id = cudaLaunchAttributeProgrammaticStreamSerialization;
    attr[0].val.programmaticStreamSerializationAllowed = 1;
    cfg.attrs = attr;
    cfg.numAttrs = 1;
    cudaLaunchKernelEx(&cfg, func, args...);
}

// ---------------- launch -----------------------------------------------------
extern "C" void kernel_launch(void* const* d_in, const int* in_sizes, int n_in,
                              void* d_out, int out_size) {
    const float* x  = (const float*)d_in[0];
    const int*   ei = (const int*)d_in[1];   // rows = ei, cols = ei + NE
    const float* W1 = (const float*)d_in[2];
    const float* b1 = (const float*)d_in[3];
    const float* W2 = (const float*)d_in[4];
    const float* b2 = (const float*)d_in[5];
    float* out = (float*)d_out;

    const int* rows = ei;
    const int* cols = ei + NE;
    const int4* cols4 = (const int4*)(ei + NE);

    __half *h1, *h2;
    float *agg1, *dinv;
    int *cnt, *rowstart, *cursor, *srcA, *bsum;
    unsigned* fdone;
    cudaGetSymbolAddress((void**)&h1,       g_h1);
    cudaGetSymbolAddress((void**)&agg1,     g_agg1);
    cudaGetSymbolAddress((void**)&h2,       g_h2);
    cudaGetSymbolAddress((void**)&dinv,     g_dinv);
    cudaGetSymbolAddress((void**)&cnt,      g_cnt);
    cudaGetSymbolAddress((void**)&rowstart, g_rowstart);
    cudaGetSymbolAddress((void**)&cursor,   g_cursor);
    cudaGetSymbolAddress((void**)&srcA,     g_src);
    cudaGetSymbolAddress((void**)&bsum,     g_bsum);
    cudaGetSymbolAddress((void**)&fdone,    g_fill_done);

    const int T = 256;
    const int SMEM1 = (128 * (C1 + 8)) * (int)sizeof(float);  // 69632
    const int SMEM2 = (128 * (C2 + 8)) * (int)sizeof(float);  // 36864
    cudaFuncSetAttribute((const void*)k_gemm_tc<C1, false>,
                         cudaFuncAttributeMaxDynamicSharedMemorySize, SMEM1);
    cudaFuncSetAttribute((const void*)k_gemm_tc<C2, true>,
                         cudaFuncAttributeMaxDynamicSharedMemorySize, SMEM2);

    const int GB = (NN + 127) / 128;          // gemm blocks (391)
    const int GW = (NN * 32 + T - 1) / T;     // gather blocks (warp/node)

    // ---- CSR build (PDL chain; semantics = stream order). No memset node:
    // cnt is statically zero-initialized; gather2 re-zeros it every run.
    launch_pdl(k_hist, (E4 + T - 1) / T, T, 0, cols4, cnt, E4);
    launch_pdl(k_scan_block, NBLK, 256, 0, (const int*)cnt, rowstart, bsum, NN);
    launch_pdl(k_finalize, NBLK, 256, 0, rowstart, cursor, (const int*)bsum,
               (const int*)cnt, dinv, NN, NE);
    // fill gridsyncs then triggers -> gemm1 overlaps fill, dinv guaranteed
    launch_pdl(k_fill, FILL_BLOCKS, T, 0, rows, cols, cursor, srcA, fdone, NE);

    // ---- layer 1 ----
    launch_pdl(k_gemm_tc<C1, false>, GB, T, SMEM1, x, W1, (const float*)dinv, h1, NN);
    launch_pdl(k_gather<C1, true, true, false>, GW, T, 0, (const __half*)h1,
               (const int*)rowstart, (const int*)srcA, (const float*)dinv,
               b1, agg1, fdone, cnt, NN);

    // ---- layer 2 ----
    launch_pdl(k_gemm_tc<C2, true>, GB, T, SMEM2, (const float*)agg1, W2,
               (const float*)dinv, h2, NN);
    launch_pdl(k_gather<C2, false, false, true>, GW, T, 0, (const __half*)h2,
               (const int*)rowstart, (const int*)srcA, (const float*)dinv,
               b2, out, fdone, cnt, NN);
}